// round 6
// baseline (speedup 1.0000x reference)
#include <cuda_runtime.h>
#include <math.h>

// Shapes (fixed): N=64, T=300, V=25, C=64, K=3, F=64, I=16, d=T*I=4800
#define SCALE_D 0.014433756729740645f   // 1/sqrt(4800)

typedef unsigned long long u64;

__device__ __forceinline__ u64 pk2(float lo, float hi) {
    u64 r; asm("mov.b64 %0, {%1, %2};" : "=l"(r) : "f"(lo), "f"(hi)); return r;
}
__device__ __forceinline__ void up2(u64 v, float& a, float& b) {
    asm("mov.b64 {%0, %1}, %2;" : "=f"(a), "=f"(b) : "l"(v));
}
__device__ __forceinline__ void fma2(u64& d, u64 a, u64 b) {
    asm("fma.rn.f32x2 %0, %1, %2, %0;" : "+l"(d) : "l"(a), "l"(b));
}

// Scratch (module-static device memory; no runtime allocation)
__device__ float g_Spart[30 * 3 * 64 * 625];   // [chunk][k][n][v*25+w] partial scores
__device__ float g_Aad[3 * 64 * 625];          // A_adapt [k][n][v*25+w]

// ---------------------------------------------------------------------------
// Kernel 1: attention score partials. Grid (30, 64), 256 threads.
// Embedding: 240 threads, 5r x 4c, FFMA2 over column pairs.
// Score: 168 threads = 84 tiles (4v x 8w) x 2 i-halves, FFMA2, smem combine.
// ---------------------------------------------------------------------------
__global__ __launch_bounds__(256) void score_kernel(
    const float* __restrict__ x,
    const float* __restrict__ Wq, const float* __restrict__ bq,
    const float* __restrict__ Wk, const float* __restrict__ bk)
{
    extern __shared__ float sm[];
    float* Gs = sm;            // [64][96] combined Wq|Wk (j<48 Q, j>=48 K)
    float* bs = Gs + 6144;     // [96]
    float* Xs = bs + 96;       // [2][25][68] padded = 3400 (reused as staging)
    float* Qt = Xs + 3400;     // [2][3][16][28] = 2688 (i-major, v contiguous)
    float* Kt = Qt + 2688;     // [2][3][16][28] = 2688, +8 pad
    // total 15024 floats = 60096 B

    const int tid = threadIdx.x;
    const int chunk = blockIdx.x;
    const int n = blockIdx.y;

    // Load combined embedding weights into smem
    for (int e = tid; e < 6144; e += 256) {
        int c = e / 96, j = e % 96;
        float v;
        if (j < 48)  v = Wq[(j >> 4) * 1024 + c * 16 + (j & 15)];
        else { int jj = j - 48; v = Wk[(jj >> 4) * 1024 + c * 16 + (jj & 15)]; }
        Gs[e] = v;
    }
    if (tid < 96) bs[tid] = (tid < 48) ? bq[tid] : bk[tid - 48];
    if (tid < 8) Kt[2688 + tid] = 0.f;   // pad after Kt (w8=3 overread)

    // Score task decode: 168 threads = 84 tiles x 2 i-halves
    const int stask = tid >> 1;          // 0..83 (for tid<168)
    const int ih    = tid & 1;
    const int kq_s  = stask / 28;
    const int rs    = stask % 28;
    const int w8_s  = rs / 7;            // 0..3 (8 w each)
    const int vp_s  = rs % 7;            // 0..6 (4 v each)
    const bool score_active = (tid < 168);

    // acc2[vi][wp] : wp = w-pair index (8 w = 4 pairs)
    u64 acc2[4][4];
#pragma unroll
    for (int a = 0; a < 4; a++)
#pragma unroll
        for (int b2 = 0; b2 < 4; b2++) acc2[a][b2] = pk2(0.f, 0.f);

    const float* xn = x + (n * 300 + chunk * 10) * 1600;

    // Embedding task decode (240 active)
    const int t2   = tid / 120;
    const int re   = tid % 120;
    const int qk   = re / 60;
    const int r2   = re % 60;
    const int rowg = r2 / 12;
    const int ic   = r2 % 12;
    const int kq_e = ic >> 2;
    const int i4   = ic & 3;
    const int gcol = qk * 12 + kq_e * 4 + i4;

    for (int step = 0; step < 5; ++step) {
        __syncthreads();
        {   // load 2 consecutive t tiles (800 float4), remap rows to stride 68
            const float4* src = (const float4*)(xn + step * 3200);
            float4* dst = (float4*)Xs;
            for (int e = tid; e < 800; e += 256) {
                int tile = e / 400, er = e % 400;
                int row = er >> 4, col = er & 15;
                dst[tile * 425 + row * 17 + col] = src[e];
            }
        }
        __syncthreads();

        // --- Q/K embedding GEMM: E = X * [Wq|Wk] + bias, 240 tasks ---
        if (tid < 240) {
            u64 acc01[5], acc23[5];
#pragma unroll
            for (int rr = 0; rr < 5; rr++) { acc01[rr] = pk2(0.f, 0.f); acc23[rr] = pk2(0.f, 0.f); }

            const float* Xb = Xs + t2 * 1700 + rowg * 340;
            const ulonglong2* G2 = (const ulonglong2*)Gs;
#pragma unroll 4
            for (int c4 = 0; c4 < 16; ++c4) {
                float4 xr[5];
#pragma unroll
                for (int rr = 0; rr < 5; ++rr)
                    xr[rr] = *(const float4*)(Xb + rr * 68 + c4 * 4);
#pragma unroll
                for (int j = 0; j < 4; ++j) {
                    ulonglong2 g = G2[(c4 * 4 + j) * 24 + gcol];
#pragma unroll
                    for (int rr = 0; rr < 5; ++rr) {
                        float xv = (j == 0) ? xr[rr].x : (j == 1) ? xr[rr].y
                                 : (j == 2) ? xr[rr].z : xr[rr].w;
                        u64 xx = pk2(xv, xv);
                        fma2(acc01[rr], xx, g.x);
                        fma2(acc23[rr], xx, g.y);
                    }
                }
            }
            const int bb0 = qk * 48 + kq_e * 16 + i4 * 4;
            const float b0 = bs[bb0], b1 = bs[bb0 + 1], b2 = bs[bb0 + 2], b3 = bs[bb0 + 3];
            float* eb = (qk ? Kt : Qt) + t2 * 1344 + kq_e * 448 + (i4 * 4) * 28;
#pragma unroll
            for (int rr = 0; rr < 5; ++rr) {
                int row = rowg * 5 + rr;
                float e0, e1, e2, e3;
                up2(acc01[rr], e0, e1);
                up2(acc23[rr], e2, e3);
                eb[row]      = e0 + b0;
                eb[28 + row] = e1 + b1;
                eb[56 + row] = e2 + b2;
                eb[84 + row] = e3 + b3;
            }
        }
        __syncthreads();

        // --- Score accumulation: S[k][4v][8w] += Q^T.K over this i-half ---
        if (score_active) {
#pragma unroll
            for (int ti = 0; ti < 2; ++ti) {
                const float* qb = Qt + ti * 1344 + kq_s * 448 + vp_s * 4;
                const float* kb = Kt + ti * 1344 + kq_s * 448 + w8_s * 8;
#pragma unroll
                for (int ii = 0; ii < 8; ++ii) {
                    int i = ih * 8 + ii;
                    float4 q = *(const float4*)(qb + i * 28);
                    ulonglong2 k01 = *(const ulonglong2*)(kb + i * 28);
                    ulonglong2 k23 = *(const ulonglong2*)(kb + i * 28 + 4);
                    u64 qx = pk2(q.x, q.x), qy = pk2(q.y, q.y);
                    u64 qz = pk2(q.z, q.z), qw = pk2(q.w, q.w);
                    fma2(acc2[0][0], qx, k01.x); fma2(acc2[0][1], qx, k01.y);
                    fma2(acc2[0][2], qx, k23.x); fma2(acc2[0][3], qx, k23.y);
                    fma2(acc2[1][0], qy, k01.x); fma2(acc2[1][1], qy, k01.y);
                    fma2(acc2[1][2], qy, k23.x); fma2(acc2[1][3], qy, k23.y);
                    fma2(acc2[2][0], qz, k01.x); fma2(acc2[2][1], qz, k01.y);
                    fma2(acc2[2][2], qz, k23.x); fma2(acc2[2][3], qz, k23.y);
                    fma2(acc2[3][0], qw, k01.x); fma2(acc2[3][1], qw, k01.y);
                    fma2(acc2[3][2], qw, k23.x); fma2(acc2[3][3], qw, k23.y);
                }
            }
        }
    }

    // --- combine i-halves via smem (Xs reused), then write chunk partials ---
    __syncthreads();
    if (score_active && ih) {
        u64* st = (u64*)Xs;
#pragma unroll
        for (int vi = 0; vi < 4; ++vi)
#pragma unroll
            for (int wp = 0; wp < 4; ++wp)
                st[stask * 16 + vi * 4 + wp] = acc2[vi][wp];
    }
    __syncthreads();
    if (score_active && !ih) {
        const u64* st = (const u64*)Xs;
        float* base = g_Spart + ((chunk * 3 + kq_s) * 64 + n) * 625;
#pragma unroll
        for (int vi = 0; vi < 4; ++vi) {
            int v = vp_s * 4 + vi;
            if (v < 25) {
#pragma unroll
                for (int wp = 0; wp < 4; ++wp) {
                    float p0, p1, o0, o1;
                    up2(acc2[vi][wp], p0, p1);
                    up2(st[stask * 16 + vi * 4 + wp], o0, o1);
                    int w = w8_s * 8 + wp * 2;
                    if (w < 25)     base[v * 25 + w]     = p0 + o0;
                    if (w + 1 < 25) base[v * 25 + w + 1] = p1 + o1;
                }
            }
        }
    }
}

// ---------------------------------------------------------------------------
// Kernel 2: reduce chunk partials (deterministic order), softmax, add A.
// ---------------------------------------------------------------------------
__global__ __launch_bounds__(128) void softmax_kernel(const float* __restrict__ A)
{
    __shared__ float S[625];
    const int b = blockIdx.x;
    const int kq = b / 64, n = b % 64;
    const int tid = threadIdx.x;

    for (int e = tid; e < 625; e += 128) {
        float s = 0.f;
        int base = ((kq * 64) + n) * 625 + e;
#pragma unroll 6
        for (int ch = 0; ch < 30; ++ch) s += g_Spart[ch * 120000 + base];
        S[e] = s;
    }
    __syncthreads();

    if (tid < 25) {
        const int v = tid;
        float m = -1e30f;
#pragma unroll
        for (int w = 0; w < 25; ++w) {
            float z = S[v * 25 + w] * SCALE_D;
            m = fmaxf(m, z);
        }
        float p[25];
        float sum = 0.f;
#pragma unroll
        for (int w = 0; w < 25; ++w) {
            p[w] = expf(S[v * 25 + w] * SCALE_D - m);
            sum += p[w];
        }
        float inv = 1.f / sum;
        float* dst = g_Aad + ((kq * 64) + n) * 625 + v * 25;
        const float* Ab = A + kq * 625 + v * 25;
#pragma unroll
        for (int w = 0; w < 25; ++w) dst[w] = Ab[w] + p[w] * inv;
    }
}

// ---------------------------------------------------------------------------
// Kernel 3: main path. Grid (25, 64), 256 threads.
// H = X*W, 240 threads, FFMA2 (column pairs).
// Y = A^T H: 224 threads = 112 tiles (4w x 4f) x 2 v-halves, FFMA2 + combine.
// ---------------------------------------------------------------------------
__global__ __launch_bounds__(256) void main_kernel(
    const float* __restrict__ x, const float* __restrict__ W,
    const float* __restrict__ b, float* __restrict__ y)
{
    extern __shared__ float sm[];
    float* Ws    = sm;             // [64][192] = 12288
    float* Xs    = Ws + 12288;     // [25][68] padded = 1700
    float* Hs    = Xs + 1700;      // [25][192] = 4800
    float* ybias = Hs + 4800;      // [25][64]  = 1600
    float* As    = ybias + 1600;   // [3][25][28] padded = 2100
    float* csum  = As + 2100;      // [3][25]+pad = 80
    float* stg   = csum + 80;      // [112][16] staging = 1792
    // total 26360 floats = 105440 B... (actual sum: 12288+1700+4800+1600+2100+80+1792 = 24360 = 97440 B)

    const int tid = threadIdx.x;
    const int n = blockIdx.y;
    const int tc = blockIdx.x;

    {   // load W (contiguous)
        const float4* src = (const float4*)W;
        float4* dst = (float4*)Ws;
        for (int e = tid; e < 3072; e += 256) dst[e] = src[e];
    }
    // load A_adapt for this n, repack to row stride 28
    for (int e = tid; e < 1875; e += 256) {
        int k = e / 625, rem = e % 625;
        int v = rem / 25, w = rem % 25;
        As[k * 700 + v * 28 + w] = g_Aad[(k * 64 + n) * 625 + rem];
    }
    // zero the w=25..27 pad columns
    for (int e = tid; e < 225; e += 256) {
        int k = e / 75, r = e % 75;
        As[k * 700 + (r / 3) * 28 + 25 + (r % 3)] = 0.f;
    }
    __syncthreads();

    if (tid < 75) {
        int k = tid / 25, w = tid % 25;
        float s = 0.f;
#pragma unroll
        for (int v = 0; v < 25; ++v) s += As[k * 700 + v * 28 + w];
        csum[tid] = s;
    }
    __syncthreads();
    for (int e = tid; e < 1600; e += 256) {
        int w = e / 64, f = e % 64;
        ybias[e] = b[f] * csum[w] + b[64 + f] * csum[25 + w] + b[128 + f] * csum[50 + w];
    }

    const int col4 = tid % 48;      // H phase (tid < 240)
    const int rowg = tid / 48;
    const int ytile = tid % 112;    // Y phase (tid < 224)
    const int vh = tid / 112;       // v-half: 0 -> v 0..12, 1 -> v 13..24
    const int w4 = ytile / 16;      // 0..6
    const int f4 = ytile % 16;      // 0..15

    for (int tt = 0; tt < 12; ++tt) {
        const int t = tc * 12 + tt;
        __syncthreads();
        {   // load X tile (400 float4), remap rows to stride 68
            const float4* src = (const float4*)(x + (n * 300 + t) * 1600);
            float4* dst = (float4*)Xs;
            for (int e = tid; e < 400; e += 256) {
                int row = e >> 4, col = e & 15;
                dst[row * 17 + col] = src[e];
            }
        }
        __syncthreads();

        // --- H = X * W : 25x192, 5 rows x float4, FFMA2 column pairs ---
        if (tid < 240) {
            u64 acc01[5], acc23[5];
#pragma unroll
            for (int r = 0; r < 5; ++r) { acc01[r] = pk2(0.f, 0.f); acc23[r] = pk2(0.f, 0.f); }
            const float* Xb = Xs + rowg * 340;
            const ulonglong2* W2 = (const ulonglong2*)Ws;
#pragma unroll 4
            for (int c4 = 0; c4 < 16; ++c4) {
                float4 xr[5];
#pragma unroll
                for (int r = 0; r < 5; ++r)
                    xr[r] = *(const float4*)(Xb + r * 68 + c4 * 4);
#pragma unroll
                for (int j = 0; j < 4; ++j) {
                    ulonglong2 wv = W2[(c4 * 4 + j) * 48 + col4];
#pragma unroll
                    for (int r = 0; r < 5; ++r) {
                        float xv = (j == 0) ? xr[r].x : (j == 1) ? xr[r].y
                                 : (j == 2) ? xr[r].z : xr[r].w;
                        u64 xx = pk2(xv, xv);
                        fma2(acc01[r], xx, wv.x);
                        fma2(acc23[r], xx, wv.y);
                    }
                }
            }
            float4* H4 = (float4*)Hs;
#pragma unroll
            for (int r = 0; r < 5; ++r) {
                float h0, h1, h2, h3;
                up2(acc01[r], h0, h1);
                up2(acc23[r], h2, h3);
                H4[(rowg * 5 + r) * 48 + col4] = make_float4(h0, h1, h2, h3);
            }
        }
        __syncthreads();

        // --- Y: 4w x 4f tiles split over 2 v-halves (224 threads) ---
        if (tid < 224) {
            const ulonglong2* H2 = (const ulonglong2*)Hs;
            const ulonglong2* yb2 = (const ulonglong2*)ybias;
            u64 s2[4][2];
#pragma unroll
            for (int j = 0; j < 4; ++j) {
                int w = w4 * 4 + j;
                if (vh == 0 && w < 25) {
                    ulonglong2 yv = yb2[w * 16 + f4];
                    s2[j][0] = yv.x; s2[j][1] = yv.y;
                } else {
                    s2[j][0] = pk2(0.f, 0.f); s2[j][1] = pk2(0.f, 0.f);
                }
            }
            const int vbeg = vh ? 13 : 0;
            const int vend = vh ? 25 : 13;
#pragma unroll
            for (int k = 0; k < 3; ++k) {
                const float* Ab = As + k * 700 + w4 * 4;
                const int hcol = k * 16 + f4;
                for (int v = vbeg; v < vend; ++v) {
                    ulonglong2 h = H2[v * 48 + hcol];
                    float4 a = *(const float4*)(Ab + v * 28);
                    u64 a0 = pk2(a.x, a.x), a1 = pk2(a.y, a.y);
                    u64 a2 = pk2(a.z, a.z), a3 = pk2(a.w, a.w);
                    fma2(s2[0][0], a0, h.x); fma2(s2[0][1], a0, h.y);
                    fma2(s2[1][0], a1, h.x); fma2(s2[1][1], a1, h.y);
                    fma2(s2[2][0], a2, h.x); fma2(s2[2][1], a2, h.y);
                    fma2(s2[3][0], a3, h.x); fma2(s2[3][1], a3, h.y);
                }
            }
            if (vh == 1) {   // stage upper-half partials
                u64* st = (u64*)stg;
#pragma unroll
                for (int j = 0; j < 4; ++j) {
                    st[ytile * 8 + j * 2]     = s2[j][0];
                    st[ytile * 8 + j * 2 + 1] = s2[j][1];
                }
            }
            __syncthreads();
            if (vh == 0) {
                const u64* st = (const u64*)stg;
                float4* yout = (float4*)(y + (n * 300 + t) * 1600);
#pragma unroll
                for (int j = 0; j < 4; ++j) {
                    int w = w4 * 4 + j;
                    if (w < 25) {
                        float p0, p1, p2, p3, o0, o1, o2, o3;
                        up2(s2[j][0], p0, p1);
                        up2(s2[j][1], p2, p3);
                        up2(st[ytile * 8 + j * 2],     o0, o1);
                        up2(st[ytile * 8 + j * 2 + 1], o2, o3);
                        yout[w * 16 + f4] = make_float4(p0 + o0, p1 + o1, p2 + o2, p3 + o3);
                    }
                }
            }
        } else {
            __syncthreads();   // match the Y-phase barrier
        }
    }
}

// ---------------------------------------------------------------------------
extern "C" void kernel_launch(void* const* d_in, const int* in_sizes, int n_in,
                              void* d_out, int out_size)
{
    const float* x  = (const float*)d_in[0];
    const float* A  = (const float*)d_in[1];
    const float* W  = (const float*)d_in[2];
    const float* b  = (const float*)d_in[3];
    const float* Wq = (const float*)d_in[4];
    const float* bq = (const float*)d_in[5];
    const float* Wk = (const float*)d_in[6];
    const float* bk = (const float*)d_in[7];
    float* y = (float*)d_out;

    const int score_smem = 15024 * 4;   // 60096 B
    const int main_smem  = 24360 * 4;   // 97440 B
    cudaFuncSetAttribute(score_kernel, cudaFuncAttributeMaxDynamicSharedMemorySize, score_smem);
    cudaFuncSetAttribute(main_kernel,  cudaFuncAttributeMaxDynamicSharedMemorySize, main_smem);

    score_kernel<<<dim3(30, 64), 256, score_smem>>>(x, Wq, bq, Wk, bk);
    softmax_kernel<<<192, 128>>>(A);
    main_kernel<<<dim3(25, 64), 256, main_smem>>>(x, W, b, y);
}